// round 9
// baseline (speedup 1.0000x reference)
#include <cuda_runtime.h>
#include <mma.h>
#include <cstdint>

using namespace nvcuda;

// ---------------------------------------------------------------------------
// LePE attention. WMMA tf32 GEMMs (n-fastest grid for L2 A-reuse),
// attention kernel with fused LePE depthwise-3x3 epilogue.
// B=16, H=W=64, C=384, HEADS=12, hd=32, IDX=0 (vertical strips).
// ---------------------------------------------------------------------------

#define C_DIM   384
#define N_HEADS 12
#define HD      32
#define B_DIM   16
#define NTOK    4096
#define L_DIM   64
#define M_TOTAL 65536
#define QKV_N   1152

// Scratch
__device__ float g_qkv[(size_t)M_TOTAL * QKV_N];   // (B*N, 3C) row-major
__device__ float g_comb[(size_t)M_TOTAL * C_DIM];  // attn_out + lepe, (B, N, C)

#define BK  16
#define PAD 20   // floats per smem row (mult of 4)

// ---------------------------------------------------------------------------
// Pure GEMM: D[m, n] = sum_k A[m, k] * Bw[n, k]  (+ bias[n] if bias != null)
// Grid: blockIdx.x = n-block (FAST -> consecutive CTAs share the A tile in L2),
//       blockIdx.y = m-block.
// 128x128 tile, BK=16 double-buffered, tf32 pre-rounded in loader.
// 8 warps (2m x 4n), warp = 4x2 wmma m16n16k8 tiles.
// ---------------------------------------------------------------------------
__global__ __launch_bounds__(256)
void gemm_wmma_kernel(const float* __restrict__ A, const float* __restrict__ Bw,
                      const float* __restrict__ bias, float* __restrict__ D,
                      int ldD)
{
    __shared__ float As[2][128 * PAD];
    __shared__ float Bs[2][128 * PAD];

    const int tid  = threadIdx.x;
    const int lane = tid & 31;
    const int warp = tid >> 5;
    const int warpM = warp >> 2;       // 0..1  -> 64 rows
    const int warpN = warp & 3;        // 0..3  -> 32 cols
    const int n0 = blockIdx.x * 128;   // n is the FAST grid dim
    const int m0 = blockIdx.y * 128;

    // loader plan: 2 (row, c4) slots per thread per matrix
    const float* aSrc[2];
    const float* bSrc[2];
    int rowIdx[2], c4Idx[2];
#pragma unroll
    for (int i = 0; i < 2; i++) {
        const int f = tid + i * 256;       // 0..511
        rowIdx[i] = f >> 2;                // 0..127
        c4Idx[i]  = f & 3;
        aSrc[i] = A + (size_t)(m0 + rowIdx[i]) * C_DIM + c4Idx[i] * 4;
        bSrc[i] = Bw + (size_t)(n0 + rowIdx[i]) * C_DIM + c4Idx[i] * 4;
    }

    wmma::fragment<wmma::accumulator, 16, 16, 8, float> acc[4][2];
#pragma unroll
    for (int tr = 0; tr < 4; tr++)
#pragma unroll
        for (int tc = 0; tc < 2; tc++)
            wmma::fill_fragment(acc[tr][tc], 0.0f);

    const int NCHUNK = C_DIM / BK;  // 24
    const int aRow = warpM * 64;
    const int bRow = warpN * 32;

    // prologue: chunk 0 -> regs (tf32-rounded) -> buf 0
    float4 avA[2], avB[2];
#pragma unroll
    for (int i = 0; i < 2; i++) {
        float4 a = *(const float4*)(aSrc[i]);
        float4 b = *(const float4*)(bSrc[i]);
        a.x = wmma::__float_to_tf32(a.x); a.y = wmma::__float_to_tf32(a.y);
        a.z = wmma::__float_to_tf32(a.z); a.w = wmma::__float_to_tf32(a.w);
        b.x = wmma::__float_to_tf32(b.x); b.y = wmma::__float_to_tf32(b.y);
        b.z = wmma::__float_to_tf32(b.z); b.w = wmma::__float_to_tf32(b.w);
        avA[i] = a; avB[i] = b;
        *(float4*)&As[0][rowIdx[i] * PAD + c4Idx[i] * 4] = a;
        *(float4*)&Bs[0][rowIdx[i] * PAD + c4Idx[i] * 4] = b;
    }
    __syncthreads();

    for (int c = 0; c < NCHUNK; c++) {
        const int buf = c & 1;
        if (c + 1 < NCHUNK) {
            const int k0g = (c + 1) * BK;
#pragma unroll
            for (int i = 0; i < 2; i++) {
                avA[i] = *(const float4*)(aSrc[i] + k0g);
                avB[i] = *(const float4*)(bSrc[i] + k0g);
            }
        }

        const float* sa = As[buf];
        const float* sb = Bs[buf];
#pragma unroll
        for (int ks = 0; ks < 2; ks++) {
            const int k0 = ks * 8;
            wmma::fragment<wmma::matrix_a, 16, 16, 8, wmma::precision::tf32,
                           wmma::row_major> af[4];
            wmma::fragment<wmma::matrix_b, 16, 16, 8, wmma::precision::tf32,
                           wmma::col_major> bf[2];
#pragma unroll
            for (int tr = 0; tr < 4; tr++)
                wmma::load_matrix_sync(af[tr], sa + (aRow + tr * 16) * PAD + k0, PAD);
#pragma unroll
            for (int tc = 0; tc < 2; tc++)
                wmma::load_matrix_sync(bf[tc], sb + (bRow + tc * 16) * PAD + k0, PAD);
#pragma unroll
            for (int tr = 0; tr < 4; tr++)
#pragma unroll
                for (int tc = 0; tc < 2; tc++)
                    wmma::mma_sync(acc[tr][tc], af[tr], bf[tc], acc[tr][tc]);
        }

        if (c + 1 < NCHUNK) {
            const int nb = (c + 1) & 1;
#pragma unroll
            for (int i = 0; i < 2; i++) {
                float4 a = avA[i], b = avB[i];
                a.x = wmma::__float_to_tf32(a.x); a.y = wmma::__float_to_tf32(a.y);
                a.z = wmma::__float_to_tf32(a.z); a.w = wmma::__float_to_tf32(a.w);
                b.x = wmma::__float_to_tf32(b.x); b.y = wmma::__float_to_tf32(b.y);
                b.z = wmma::__float_to_tf32(b.z); b.w = wmma::__float_to_tf32(b.w);
                *(float4*)&As[nb][rowIdx[i] * PAD + c4Idx[i] * 4] = a;
                *(float4*)&Bs[nb][rowIdx[i] * PAD + c4Idx[i] * 4] = b;
            }
            __syncthreads();
        }
    }

    // ---- epilogue ----
    if (bias == nullptr) {
#pragma unroll
        for (int tr = 0; tr < 4; tr++)
#pragma unroll
            for (int tc = 0; tc < 2; tc++) {
                const int mBase = m0 + warpM * 64 + tr * 16;
                const int nBase = n0 + warpN * 32 + tc * 16;
                wmma::store_matrix_sync(D + (size_t)mBase * ldD + nBase,
                                        acc[tr][tc], ldD, wmma::mem_row_major);
            }
    } else {
        __syncthreads();   // smem free; reuse As[0] as staging
        float* stage = &As[0][0] + warp * 256;   // 16x16 per warp
#pragma unroll
        for (int tr = 0; tr < 4; tr++) {
#pragma unroll
            for (int tc = 0; tc < 2; tc++) {
                const int mBase = m0 + warpM * 64 + tr * 16;
                const int nBase = n0 + warpN * 32 + tc * 16;
                wmma::store_matrix_sync(stage, acc[tr][tc], 16, wmma::mem_row_major);
                __syncwarp();
#pragma unroll
                for (int t = 0; t < 2; t++) {
                    const int idx = lane + t * 32;   // float4 index 0..63
                    const int r  = idx >> 2;
                    const int c4 = idx & 3;
                    float4 v = ((const float4*)stage)[idx];
                    const float4 b4 = *(const float4*)&bias[nBase + c4 * 4];
                    v.x += b4.x; v.y += b4.y; v.z += b4.z; v.w += b4.w;
                    *(float4*)&D[(size_t)(mBase + r) * ldD + nBase + c4 * 4] = v;
                }
                __syncwarp();
            }
        }
    }
}

// ---------------------------------------------------------------------------
// Attention + fused LePE: one block per (s, head), s = b*64 + w.
// Gathers Q/K/V from g_qkv rows (b*4096 + l*64 + w).
// Output row n = b*4096 + w*64 + l gets: attn_out(l, head-slice)
//   + lepe at natural token (hh=w, ww=l) for the head's 32 channels.
// ---------------------------------------------------------------------------
__global__ __launch_bounds__(256) void attn_lepe_kernel(
    const float* __restrict__ x, const float* __restrict__ lw,
    const float* __restrict__ lb)
{
    __shared__ float Qs[64][33];
    __shared__ float Ks[64][33];
    __shared__ float Vs[64][33];
    __shared__ float P[64][65];
    __shared__ float Xs[3][66][32];   // x neighborhood: dy, ww+1, channel

    const int g    = blockIdx.x;           // s*12 + head
    const int tid  = threadIdx.x;
    const int s    = g / N_HEADS;
    const int head = g - s * N_HEADS;
    const int b    = s >> 6;
    const int w    = s & 63;
    const int cBase = head * HD;

    // gather Q/K/V: token l of strip -> row b*4096 + l*64 + w
    const size_t rowBase = (size_t)(b << 12) + w;   // + l*64
    for (int i = tid; i < 2048; i += 256) {
        const int l = i >> 5, d = i & 31;
        const size_t roff = (rowBase + (size_t)l * 64) * QKV_N + cBase + d;
        Qs[l][d] = g_qkv[roff];
        Ks[l][d] = g_qkv[roff + C_DIM];
        Vs[l][d] = g_qkv[roff + 2 * C_DIM];
    }

    // load x neighborhood for LePE: rows y = w-1..w+1, tokens ww = -1..64
    for (int i = tid; i < 3 * 66 * 32; i += 256) {
        const int dyi = i / (66 * 32);
        const int r   = i - dyi * (66 * 32);
        const int t1  = r >> 5;          // 0..65
        const int d   = r & 31;
        const int y   = w + dyi - 1;
        const int tt  = t1 - 1;          // -1..64
        float v = 0.f;
        if (y >= 0 && y < 64 && tt >= 0 && tt < 64)
            v = x[(size_t)((b << 12) + (y << 6) + tt) * C_DIM + cBase + d];
        Xs[dyi][t1][d] = v;
    }
    __syncthreads();

    const float scale = 0.17677669529663687f;  // 1/sqrt(32)
    for (int idx = tid; idx < 4096; idx += 256) {
        const int l = idx >> 6, m = idx & 63;
        float sc = 0.f;
#pragma unroll
        for (int d = 0; d < 32; d++) sc += Qs[l][d] * Ks[m][d];
        P[l][m] = sc * scale;
    }
    __syncthreads();

    const int warp = tid >> 5, lane = tid & 31;
#pragma unroll
    for (int rr = 0; rr < 8; rr++) {
        const int l = warp * 8 + rr;
        float v0 = P[l][lane], v1 = P[l][lane + 32];
        float mx = fmaxf(v0, v1);
#pragma unroll
        for (int o = 16; o; o >>= 1) mx = fmaxf(mx, __shfl_xor_sync(0xFFFFFFFFu, mx, o));
        const float e0 = __expf(v0 - mx);
        const float e1 = __expf(v1 - mx);
        float sm = e0 + e1;
#pragma unroll
        for (int o = 16; o; o >>= 1) sm += __shfl_xor_sync(0xFFFFFFFFu, sm, o);
        const float inv = 1.f / sm;
        P[l][lane]      = e0 * inv;
        P[l][lane + 32] = e1 * inv;
    }
    __syncthreads();

    // per-thread fixed channel: idx & 31 == tid & 31 for stride-256 loop
    const int dch = tid & 31;
    const int cg  = cBase + dch;
    float w9[9];
#pragma unroll
    for (int k = 0; k < 9; k++) w9[k] = lw[cg * 9 + k];
    const float bch = lb[cg];

    float* dst = g_comb + (size_t)((b << 12) + (w << 6)) * C_DIM + cBase;
    for (int idx = tid; idx < 2048; idx += 256) {
        const int l = idx >> 5, d = idx & 31;   // d == dch
        float acc = bch;
#pragma unroll
        for (int m = 0; m < 64; m++) acc += P[l][m] * Vs[m][d];
        // lepe: dy in {0,1,2} -> y=w+dy-1 (row dyi), dx -> token l+dx-1 (idx l+dx)
#pragma unroll
        for (int dy = 0; dy < 3; dy++)
#pragma unroll
            for (int dx = 0; dx < 3; dx++)
                acc += Xs[dy][l + dx][d] * w9[dy * 3 + dx];
        dst[(size_t)l * C_DIM + d] = acc;
    }
}

// ---------------------------------------------------------------------------
extern "C" void kernel_launch(void* const* d_in, const int* in_sizes, int n_in,
                              void* d_out, int out_size)
{
    const float* x      = (const float*)d_in[0];
    const float* qkv_w  = (const float*)d_in[1];
    const float* proj_w = (const float*)d_in[2];
    const float* proj_b = (const float*)d_in[3];
    const float* lepe_w = (const float*)d_in[4];
    const float* lepe_b = (const float*)d_in[5];
    float* out = (float*)d_out;
    (void)in_sizes; (void)n_in; (void)out_size;

    float* qkv_out;
    cudaGetSymbolAddress((void**)&qkv_out, g_qkv);
    float* comb;
    cudaGetSymbolAddress((void**)&comb, g_comb);

    // qkv: (65536 x 384) @ (1152 x 384)^T -> (65536 x 1152); n-fast grid
    dim3 g_qkv_grid(QKV_N / 128, M_TOTAL / 128);   // (9, 512)
    gemm_wmma_kernel<<<g_qkv_grid, 256>>>(x, qkv_w, nullptr, qkv_out, QKV_N);

    attn_lepe_kernel<<<B_DIM * 64 * N_HEADS, 256>>>(x, lepe_w, lepe_b);

    // proj: (65536 x 384) @ (384 x 384)^T + b -> out; n-fast grid
    dim3 g_proj_grid(C_DIM / 128, M_TOTAL / 128);  // (3, 512)
    gemm_wmma_kernel<<<g_proj_grid, 256>>>(comb, proj_w, proj_b, out, C_DIM);
}

// round 10
// speedup vs baseline: 1.0146x; 1.0146x over previous
#include <cuda_runtime.h>
#include <mma.h>
#include <cstdint>

using namespace nvcuda;

// ---------------------------------------------------------------------------
// LePE attention. WMMA tf32 GEMMs, n-fastest grid (L2 A-reuse), NO explicit
// tf32 rounding (HW truncates fp32 -> tf32 inside HMMA; saves 32 cvt/thread
// per chunk). Separate lean attn + lepe kernels (R8-proven).
// B=16, H=W=64, C=384, HEADS=12, hd=32, IDX=0 (vertical strips).
// ---------------------------------------------------------------------------

#define C_DIM   384
#define N_HEADS 12
#define HD      32
#define B_DIM   16
#define NTOK    4096
#define L_DIM   64
#define M_TOTAL 65536
#define QKV_N   1152

// Scratch
__device__ float g_qkv[(size_t)M_TOTAL * QKV_N];   // (B*N, 3C) row-major
__device__ float g_comb[(size_t)M_TOTAL * C_DIM];  // attn_out + lepe, (B, N, C)

#define BK  16
#define PAD 20   // floats per smem row (mult of 4)

// ---------------------------------------------------------------------------
// Pure GEMM: D[m, n] = sum_k A[m, k] * Bw[n, k]  (+ bias[n] if bias != null)
// Grid: blockIdx.x = n-block (FAST: consecutive CTAs share A tile in L2).
// 128x128 tile, BK=16 double-buffered, raw fp32 into tf32 fragments.
// 8 warps (2m x 4n), warp = 4x2 wmma m16n16k8 tiles.
// ---------------------------------------------------------------------------
__global__ __launch_bounds__(256)
void gemm_wmma_kernel(const float* __restrict__ A, const float* __restrict__ Bw,
                      const float* __restrict__ bias, float* __restrict__ D,
                      int ldD)
{
    __shared__ float As[2][128 * PAD];
    __shared__ float Bs[2][128 * PAD];

    const int tid  = threadIdx.x;
    const int lane = tid & 31;
    const int warp = tid >> 5;
    const int warpM = warp >> 2;       // 0..1  -> 64 rows
    const int warpN = warp & 3;        // 0..3  -> 32 cols
    const int n0 = blockIdx.x * 128;   // n fast
    const int m0 = blockIdx.y * 128;

    // loader plan: 2 (row, c4) slots per thread per matrix
    const float* aSrc[2];
    const float* bSrc[2];
    int rowIdx[2], c4Idx[2];
#pragma unroll
    for (int i = 0; i < 2; i++) {
        const int f = tid + i * 256;       // 0..511
        rowIdx[i] = f >> 2;                // 0..127
        c4Idx[i]  = f & 3;
        aSrc[i] = A + (size_t)(m0 + rowIdx[i]) * C_DIM + c4Idx[i] * 4;
        bSrc[i] = Bw + (size_t)(n0 + rowIdx[i]) * C_DIM + c4Idx[i] * 4;
    }

    wmma::fragment<wmma::accumulator, 16, 16, 8, float> acc[4][2];
#pragma unroll
    for (int tr = 0; tr < 4; tr++)
#pragma unroll
        for (int tc = 0; tc < 2; tc++)
            wmma::fill_fragment(acc[tr][tc], 0.0f);

    const int NCHUNK = C_DIM / BK;  // 24
    const int aRow = warpM * 64;
    const int bRow = warpN * 32;

    // prologue: chunk 0 -> buf 0 (raw fp32, no cvt)
    float4 avA[2], avB[2];
#pragma unroll
    for (int i = 0; i < 2; i++) {
        avA[i] = *(const float4*)(aSrc[i]);
        avB[i] = *(const float4*)(bSrc[i]);
        *(float4*)&As[0][rowIdx[i] * PAD + c4Idx[i] * 4] = avA[i];
        *(float4*)&Bs[0][rowIdx[i] * PAD + c4Idx[i] * 4] = avB[i];
    }
    __syncthreads();

    for (int c = 0; c < NCHUNK; c++) {
        const int buf = c & 1;
        if (c + 1 < NCHUNK) {
            const int k0g = (c + 1) * BK;
#pragma unroll
            for (int i = 0; i < 2; i++) {
                avA[i] = *(const float4*)(aSrc[i] + k0g);
                avB[i] = *(const float4*)(bSrc[i] + k0g);
            }
        }

        const float* sa = As[buf];
        const float* sb = Bs[buf];
#pragma unroll
        for (int ks = 0; ks < 2; ks++) {
            const int k0 = ks * 8;
            wmma::fragment<wmma::matrix_a, 16, 16, 8, wmma::precision::tf32,
                           wmma::row_major> af[4];
            wmma::fragment<wmma::matrix_b, 16, 16, 8, wmma::precision::tf32,
                           wmma::col_major> bf[2];
#pragma unroll
            for (int tr = 0; tr < 4; tr++)
                wmma::load_matrix_sync(af[tr], sa + (aRow + tr * 16) * PAD + k0, PAD);
#pragma unroll
            for (int tc = 0; tc < 2; tc++)
                wmma::load_matrix_sync(bf[tc], sb + (bRow + tc * 16) * PAD + k0, PAD);
#pragma unroll
            for (int tr = 0; tr < 4; tr++)
#pragma unroll
                for (int tc = 0; tc < 2; tc++)
                    wmma::mma_sync(acc[tr][tc], af[tr], bf[tc], acc[tr][tc]);
        }

        if (c + 1 < NCHUNK) {
            const int nb = (c + 1) & 1;
#pragma unroll
            for (int i = 0; i < 2; i++) {
                *(float4*)&As[nb][rowIdx[i] * PAD + c4Idx[i] * 4] = avA[i];
                *(float4*)&Bs[nb][rowIdx[i] * PAD + c4Idx[i] * 4] = avB[i];
            }
            __syncthreads();
        }
    }

    // ---- epilogue ----
    if (bias == nullptr) {
#pragma unroll
        for (int tr = 0; tr < 4; tr++)
#pragma unroll
            for (int tc = 0; tc < 2; tc++) {
                const int mBase = m0 + warpM * 64 + tr * 16;
                const int nBase = n0 + warpN * 32 + tc * 16;
                wmma::store_matrix_sync(D + (size_t)mBase * ldD + nBase,
                                        acc[tr][tc], ldD, wmma::mem_row_major);
            }
    } else {
        __syncthreads();   // smem free; reuse As[0] as staging
        float* stage = &As[0][0] + warp * 256;   // 16x16 per warp
#pragma unroll
        for (int tr = 0; tr < 4; tr++) {
#pragma unroll
            for (int tc = 0; tc < 2; tc++) {
                const int mBase = m0 + warpM * 64 + tr * 16;
                const int nBase = n0 + warpN * 32 + tc * 16;
                wmma::store_matrix_sync(stage, acc[tr][tc], 16, wmma::mem_row_major);
                __syncwarp();
#pragma unroll
                for (int t = 0; t < 2; t++) {
                    const int idx = lane + t * 32;   // float4 index 0..63
                    const int r  = idx >> 2;
                    const int c4 = idx & 3;
                    float4 v = ((const float4*)stage)[idx];
                    const float4 b4 = *(const float4*)&bias[nBase + c4 * 4];
                    v.x += b4.x; v.y += b4.y; v.z += b4.z; v.w += b4.w;
                    *(float4*)&D[(size_t)(mBase + r) * ldD + nBase + c4 * 4] = v;
                }
                __syncwarp();
            }
        }
    }
}

// ---------------------------------------------------------------------------
// Attention: one block per (s, head), s = b*64 + w. L=64, hd=32. (R8-proven)
// ---------------------------------------------------------------------------
__global__ __launch_bounds__(256) void attn_kernel()
{
    __shared__ float Qs[64][33];
    __shared__ float Ks[64][33];
    __shared__ float Vs[64][33];
    __shared__ float P[64][65];

    const int g    = blockIdx.x;           // s*12 + head
    const int tid  = threadIdx.x;
    const int s    = g / N_HEADS;
    const int head = g - s * N_HEADS;
    const int b    = s >> 6;
    const int w    = s & 63;

    const size_t rowBase = (size_t)(b << 12) + w;   // + l*64
    const int colQ = head * HD;
    for (int i = tid; i < 2048; i += 256) {
        const int l = i >> 5, d = i & 31;
        const size_t roff = (rowBase + (size_t)l * 64) * QKV_N + colQ + d;
        Qs[l][d] = g_qkv[roff];
        Ks[l][d] = g_qkv[roff + C_DIM];
        Vs[l][d] = g_qkv[roff + 2 * C_DIM];
    }
    __syncthreads();

    const float scale = 0.17677669529663687f;  // 1/sqrt(32)
    for (int idx = tid; idx < 4096; idx += 256) {
        const int l = idx >> 6, m = idx & 63;
        float sc = 0.f;
#pragma unroll
        for (int d = 0; d < 32; d++) sc += Qs[l][d] * Ks[m][d];
        P[l][m] = sc * scale;
    }
    __syncthreads();

    const int warp = tid >> 5, lane = tid & 31;
#pragma unroll
    for (int rr = 0; rr < 8; rr++) {
        const int l = warp * 8 + rr;
        float v0 = P[l][lane], v1 = P[l][lane + 32];
        float mx = fmaxf(v0, v1);
#pragma unroll
        for (int o = 16; o; o >>= 1) mx = fmaxf(mx, __shfl_xor_sync(0xFFFFFFFFu, mx, o));
        const float e0 = __expf(v0 - mx);
        const float e1 = __expf(v1 - mx);
        float sm = e0 + e1;
#pragma unroll
        for (int o = 16; o; o >>= 1) sm += __shfl_xor_sync(0xFFFFFFFFu, sm, o);
        const float inv = 1.f / sm;
        P[l][lane]      = e0 * inv;
        P[l][lane + 32] = e1 * inv;
    }
    __syncthreads();

    float* dst = g_comb + (size_t)((b << 12) + (w << 6)) * C_DIM + head * HD;
    for (int idx = tid; idx < 2048; idx += 256) {
        const int l = idx >> 5, d = idx & 31;
        float acc = 0.f;
#pragma unroll
        for (int m = 0; m < 64; m++) acc += P[l][m] * Vs[m][d];
        dst[(size_t)l * C_DIM + d] = acc;
    }
}

// ---------------------------------------------------------------------------
// LePE: depthwise 3x3, += into g_comb. (R8-proven)
// ---------------------------------------------------------------------------
__global__ __launch_bounds__(C_DIM) void lepe_kernel(
    const float* __restrict__ x, const float* __restrict__ lw,
    const float* __restrict__ lb)
{
    const int n  = blockIdx.x;
    const int c  = threadIdx.x;
    const int b  = n >> 12;
    const int sp = n & 4095;
    const int hh = sp >> 6;
    const int ww = sp & 63;

    float acc = lb[c];
    const float* wc = lw + c * 9;
    const size_t xbase = (size_t)(b << 12) * C_DIM;

#pragma unroll
    for (int dy = -1; dy <= 1; dy++) {
        const int y = hh + dy;
        if (y < 0 || y > 63) continue;
#pragma unroll
        for (int dx = -1; dx <= 1; dx++) {
            const int xx = ww + dx;
            if (xx < 0 || xx > 63) continue;
            acc += x[xbase + (size_t)((y << 6) + xx) * C_DIM + c] *
                   wc[(dy + 1) * 3 + (dx + 1)];
        }
    }
    g_comb[(size_t)n * C_DIM + c] += acc;
}

// ---------------------------------------------------------------------------
extern "C" void kernel_launch(void* const* d_in, const int* in_sizes, int n_in,
                              void* d_out, int out_size)
{
    const float* x      = (const float*)d_in[0];
    const float* qkv_w  = (const float*)d_in[1];
    const float* proj_w = (const float*)d_in[2];
    const float* proj_b = (const float*)d_in[3];
    const float* lepe_w = (const float*)d_in[4];
    const float* lepe_b = (const float*)d_in[5];
    float* out = (float*)d_out;
    (void)in_sizes; (void)n_in; (void)out_size;

    float* qkv_out;
    cudaGetSymbolAddress((void**)&qkv_out, g_qkv);
    float* comb;
    cudaGetSymbolAddress((void**)&comb, g_comb);

    // qkv: (65536 x 384) @ (1152 x 384)^T -> (65536 x 1152); n-fast grid
    dim3 g_qkv_grid(QKV_N / 128, M_TOTAL / 128);   // (9, 512)
    gemm_wmma_kernel<<<g_qkv_grid, 256>>>(x, qkv_w, nullptr, qkv_out, QKV_N);

    attn_kernel<<<B_DIM * 64 * N_HEADS, 256>>>();   // 12288 blocks

    lepe_kernel<<<B_DIM * NTOK, C_DIM>>>(x, lepe_w, lepe_b);

    // proj: (65536 x 384) @ (384 x 384)^T + b -> out; n-fast grid
    dim3 g_proj_grid(C_DIM / 128, M_TOTAL / 128);  // (3, 512)
    gemm_wmma_kernel<<<g_proj_grid, 256>>>(comb, proj_w, proj_b, out, C_DIM);
}

// round 11
// speedup vs baseline: 1.4604x; 1.4394x over previous
#include <cuda_runtime.h>
#include <cuda_fp16.h>
#include <mma.h>
#include <cstdint>

using namespace nvcuda;

// ---------------------------------------------------------------------------
// LePE attention. GEMMs via WMMA fp16 (m16n16k16, fp32 accum, LDSM fragment
// path), n-fastest grid for L2 A-reuse. fp16 rn conversion in loader keeps
// 11-bit mantissa (same as tf32-rna; rel_err ~3e-4).
// B=16, H=W=64, C=384, HEADS=12, hd=32, IDX=0 (vertical strips).
// ---------------------------------------------------------------------------

#define C_DIM   384
#define N_HEADS 12
#define HD      32
#define B_DIM   16
#define NTOK    4096
#define L_DIM   64
#define M_TOTAL 65536
#define QKV_N   1152

// Scratch
__device__ float g_qkv[(size_t)M_TOTAL * QKV_N];   // (B*N, 3C) row-major
__device__ float g_comb[(size_t)M_TOTAL * C_DIM];  // attn_out + lepe, (B, N, C)

#define BK    32
#define PAD_H 40   // halves per smem row: 80B row stride (16B multiple)

// pack 8 floats -> 8 halves (rn) in a uint4
__device__ __forceinline__ uint4 pack8(const float4 f0, const float4 f1) {
    __half2 h0 = __floats2half2_rn(f0.x, f0.y);
    __half2 h1 = __floats2half2_rn(f0.z, f0.w);
    __half2 h2 = __floats2half2_rn(f1.x, f1.y);
    __half2 h3 = __floats2half2_rn(f1.z, f1.w);
    uint4 u;
    u.x = *reinterpret_cast<uint32_t*>(&h0);
    u.y = *reinterpret_cast<uint32_t*>(&h1);
    u.z = *reinterpret_cast<uint32_t*>(&h2);
    u.w = *reinterpret_cast<uint32_t*>(&h3);
    return u;
}

// ---------------------------------------------------------------------------
// Pure GEMM: D[m, n] = sum_k A[m, k] * Bw[n, k]  (+ bias[n] if bias != null)
// Grid: blockIdx.x = n-block (FAST: consecutive CTAs share A tile in L2).
// 128x128 tile, BK=32 double-buffered fp16 smem, register prefetch.
// 8 warps (2m x 4n), warp = 4x2 wmma m16n16k16 tiles.
// ---------------------------------------------------------------------------
__global__ __launch_bounds__(256)
void gemm_wmma_kernel(const float* __restrict__ A, const float* __restrict__ Bw,
                      const float* __restrict__ bias, float* __restrict__ D,
                      int ldD)
{
    __shared__ __half As[2][128 * PAD_H];
    __shared__ __half Bs[2][128 * PAD_H];

    const int tid  = threadIdx.x;
    const int lane = tid & 31;
    const int warp = tid >> 5;
    const int warpM = warp >> 2;       // 0..1  -> 64 rows
    const int warpN = warp & 3;        // 0..3  -> 32 cols
    const int n0 = blockIdx.x * 128;   // n fast
    const int m0 = blockIdx.y * 128;

    // loader plan: thread -> (row, halfIdx); halfIdx selects 16-col group
    const int row   = tid >> 1;        // 0..127
    const int hIdx  = tid & 1;         // 0..1
    const float* aSrc = A + (size_t)(m0 + row) * C_DIM + hIdx * 16;
    const float* bSrc = Bw + (size_t)(n0 + row) * C_DIM + hIdx * 16;
    const int smOff = row * PAD_H + hIdx * 16;   // in halves

    wmma::fragment<wmma::accumulator, 16, 16, 16, float> acc[4][2];
#pragma unroll
    for (int tr = 0; tr < 4; tr++)
#pragma unroll
        for (int tc = 0; tc < 2; tc++)
            wmma::fill_fragment(acc[tr][tc], 0.0f);

    const int NCHUNK = C_DIM / BK;  // 12
    const int aRow = warpM * 64;
    const int bRow = warpN * 32;

    // prologue: chunk 0 -> packed regs -> buf 0
    uint4 pA0, pA1, pB0, pB1;
    {
        float4 a0 = *(const float4*)(aSrc + 0);
        float4 a1 = *(const float4*)(aSrc + 4);
        float4 a2 = *(const float4*)(aSrc + 8);
        float4 a3 = *(const float4*)(aSrc + 12);
        float4 b0 = *(const float4*)(bSrc + 0);
        float4 b1 = *(const float4*)(bSrc + 4);
        float4 b2 = *(const float4*)(bSrc + 8);
        float4 b3 = *(const float4*)(bSrc + 12);
        pA0 = pack8(a0, a1); pA1 = pack8(a2, a3);
        pB0 = pack8(b0, b1); pB1 = pack8(b2, b3);
        *(uint4*)&As[0][smOff]     = pA0;
        *(uint4*)&As[0][smOff + 8] = pA1;
        *(uint4*)&Bs[0][smOff]     = pB0;
        *(uint4*)&Bs[0][smOff + 8] = pB1;
    }
    __syncthreads();

    for (int c = 0; c < NCHUNK; c++) {
        const int buf = c & 1;
        if (c + 1 < NCHUNK) {
            const int k0g = (c + 1) * BK;
            float4 a0 = *(const float4*)(aSrc + k0g + 0);
            float4 a1 = *(const float4*)(aSrc + k0g + 4);
            float4 a2 = *(const float4*)(aSrc + k0g + 8);
            float4 a3 = *(const float4*)(aSrc + k0g + 12);
            float4 b0 = *(const float4*)(bSrc + k0g + 0);
            float4 b1 = *(const float4*)(bSrc + k0g + 4);
            float4 b2 = *(const float4*)(bSrc + k0g + 8);
            float4 b3 = *(const float4*)(bSrc + k0g + 12);
            pA0 = pack8(a0, a1); pA1 = pack8(a2, a3);
            pB0 = pack8(b0, b1); pB1 = pack8(b2, b3);
        }

        const __half* sa = As[buf];
        const __half* sb = Bs[buf];
#pragma unroll
        for (int ks = 0; ks < 2; ks++) {
            const int k0 = ks * 16;
            wmma::fragment<wmma::matrix_a, 16, 16, 16, __half,
                           wmma::row_major> af[4];
            wmma::fragment<wmma::matrix_b, 16, 16, 16, __half,
                           wmma::col_major> bf[2];
#pragma unroll
            for (int tr = 0; tr < 4; tr++)
                wmma::load_matrix_sync(af[tr], sa + (aRow + tr * 16) * PAD_H + k0,
                                       PAD_H);
#pragma unroll
            for (int tc = 0; tc < 2; tc++)
                wmma::load_matrix_sync(bf[tc], sb + (bRow + tc * 16) * PAD_H + k0,
                                       PAD_H);
#pragma unroll
            for (int tr = 0; tr < 4; tr++)
#pragma unroll
                for (int tc = 0; tc < 2; tc++)
                    wmma::mma_sync(acc[tr][tc], af[tr], bf[tc], acc[tr][tc]);
        }

        if (c + 1 < NCHUNK) {
            const int nb = (c + 1) & 1;
            *(uint4*)&As[nb][smOff]     = pA0;
            *(uint4*)&As[nb][smOff + 8] = pA1;
            *(uint4*)&Bs[nb][smOff]     = pB0;
            *(uint4*)&Bs[nb][smOff + 8] = pB1;
            __syncthreads();
        }
    }

    // ---- epilogue ----
    if (bias == nullptr) {
#pragma unroll
        for (int tr = 0; tr < 4; tr++)
#pragma unroll
            for (int tc = 0; tc < 2; tc++) {
                const int mBase = m0 + warpM * 64 + tr * 16;
                const int nBase = n0 + warpN * 32 + tc * 16;
                wmma::store_matrix_sync(D + (size_t)mBase * ldD + nBase,
                                        acc[tr][tc], ldD, wmma::mem_row_major);
            }
    } else {
        __syncthreads();   // smem free; reuse As as fp32 staging (warp*256 floats)
        float* stage = reinterpret_cast<float*>(&As[0][0]) + warp * 256;
#pragma unroll
        for (int tr = 0; tr < 4; tr++) {
#pragma unroll
            for (int tc = 0; tc < 2; tc++) {
                const int mBase = m0 + warpM * 64 + tr * 16;
                const int nBase = n0 + warpN * 32 + tc * 16;
                wmma::store_matrix_sync(stage, acc[tr][tc], 16, wmma::mem_row_major);
                __syncwarp();
#pragma unroll
                for (int t = 0; t < 2; t++) {
                    const int idx = lane + t * 32;   // float4 index 0..63
                    const int r  = idx >> 2;
                    const int c4 = idx & 3;
                    float4 v = ((const float4*)stage)[idx];
                    const float4 b4 = *(const float4*)&bias[nBase + c4 * 4];
                    v.x += b4.x; v.y += b4.y; v.z += b4.z; v.w += b4.w;
                    *(float4*)&D[(size_t)(mBase + r) * ldD + nBase + c4 * 4] = v;
                }
                __syncwarp();
            }
        }
    }
}

// ---------------------------------------------------------------------------
// Attention: one block per (s, head), s = b*64 + w. L=64, hd=32.
// ---------------------------------------------------------------------------
__global__ __launch_bounds__(256) void attn_kernel()
{
    __shared__ float Qs[64][33];
    __shared__ float Ks[64][33];
    __shared__ float Vs[64][33];
    __shared__ float P[64][65];

    const int g    = blockIdx.x;           // s*12 + head
    const int tid  = threadIdx.x;
    const int s    = g / N_HEADS;
    const int head = g - s * N_HEADS;
    const int b    = s >> 6;
    const int w    = s & 63;

    const size_t rowBase = (size_t)(b << 12) + w;   // + l*64
    const int colQ = head * HD;
    for (int i = tid; i < 2048; i += 256) {
        const int l = i >> 5, d = i & 31;
        const size_t roff = (rowBase + (size_t)l * 64) * QKV_N + colQ + d;
        Qs[l][d] = g_qkv[roff];
        Ks[l][d] = g_qkv[roff + C_DIM];
        Vs[l][d] = g_qkv[roff + 2 * C_DIM];
    }
    __syncthreads();

    const float scale = 0.17677669529663687f;  // 1/sqrt(32)
    for (int idx = tid; idx < 4096; idx += 256) {
        const int l = idx >> 6, m = idx & 63;
        float sc = 0.f;
#pragma unroll
        for (int d = 0; d < 32; d++) sc += Qs[l][d] * Ks[m][d];
        P[l][m] = sc * scale;
    }
    __syncthreads();

    const int warp = tid >> 5, lane = tid & 31;
#pragma unroll
    for (int rr = 0; rr < 8; rr++) {
        const int l = warp * 8 + rr;
        float v0 = P[l][lane], v1 = P[l][lane + 32];
        float mx = fmaxf(v0, v1);
#pragma unroll
        for (int o = 16; o; o >>= 1) mx = fmaxf(mx, __shfl_xor_sync(0xFFFFFFFFu, mx, o));
        const float e0 = __expf(v0 - mx);
        const float e1 = __expf(v1 - mx);
        float sm = e0 + e1;
#pragma unroll
        for (int o = 16; o; o >>= 1) sm += __shfl_xor_sync(0xFFFFFFFFu, sm, o);
        const float inv = 1.f / sm;
        P[l][lane]      = e0 * inv;
        P[l][lane + 32] = e1 * inv;
    }
    __syncthreads();

    float* dst = g_comb + (size_t)((b << 12) + (w << 6)) * C_DIM + head * HD;
    for (int idx = tid; idx < 2048; idx += 256) {
        const int l = idx >> 5, d = idx & 31;
        float acc = 0.f;
#pragma unroll
        for (int m = 0; m < 64; m++) acc += P[l][m] * Vs[m][d];
        dst[(size_t)l * C_DIM + d] = acc;
    }
}

// ---------------------------------------------------------------------------
// LePE: depthwise 3x3, += into g_comb.
// ---------------------------------------------------------------------------
__global__ __launch_bounds__(C_DIM) void lepe_kernel(
    const float* __restrict__ x, const float* __restrict__ lw,
    const float* __restrict__ lb)
{
    const int n  = blockIdx.x;
    const int c  = threadIdx.x;
    const int b  = n >> 12;
    const int sp = n & 4095;
    const int hh = sp >> 6;
    const int ww = sp & 63;

    float acc = lb[c];
    const float* wc = lw + c * 9;
    const size_t xbase = (size_t)(b << 12) * C_DIM;

#pragma unroll
    for (int dy = -1; dy <= 1; dy++) {
        const int y = hh + dy;
        if (y < 0 || y > 63) continue;
#pragma unroll
        for (int dx = -1; dx <= 1; dx++) {
            const int xx = ww + dx;
            if (xx < 0 || xx > 63) continue;
            acc += x[xbase + (size_t)((y << 6) + xx) * C_DIM + c] *
                   wc[(dy + 1) * 3 + (dx + 1)];
        }
    }
    g_comb[(size_t)n * C_DIM + c] += acc;
}

// ---------------------------------------------------------------------------
extern "C" void kernel_launch(void* const* d_in, const int* in_sizes, int n_in,
                              void* d_out, int out_size)
{
    const float* x      = (const float*)d_in[0];
    const float* qkv_w  = (const float*)d_in[1];
    const float* proj_w = (const float*)d_in[2];
    const float* proj_b = (const float*)d_in[3];
    const float* lepe_w = (const float*)d_in[4];
    const float* lepe_b = (const float*)d_in[5];
    float* out = (float*)d_out;
    (void)in_sizes; (void)n_in; (void)out_size;

    float* qkv_out;
    cudaGetSymbolAddress((void**)&qkv_out, g_qkv);
    float* comb;
    cudaGetSymbolAddress((void**)&comb, g_comb);

    // qkv: (65536 x 384) @ (1152 x 384)^T -> (65536 x 1152); n-fast grid
    dim3 g_qkv_grid(QKV_N / 128, M_TOTAL / 128);   // (9, 512)
    gemm_wmma_kernel<<<g_qkv_grid, 256>>>(x, qkv_w, nullptr, qkv_out, QKV_N);

    attn_kernel<<<B_DIM * 64 * N_HEADS, 256>>>();   // 12288 blocks

    lepe_kernel<<<B_DIM * NTOK, C_DIM>>>(x, lepe_w, lepe_b);

    // proj: (65536 x 384) @ (384 x 384)^T + b -> out; n-fast grid
    dim3 g_proj_grid(C_DIM / 128, M_TOTAL / 128);  // (3, 512)
    gemm_wmma_kernel<<<g_proj_grid, 256>>>(comb, proj_w, proj_b, out, C_DIM);
}

// round 12
// speedup vs baseline: 2.0876x; 1.4295x over previous
#include <cuda_runtime.h>
#include <cuda_fp16.h>
#include <mma.h>
#include <cstdint>

using namespace nvcuda;

// ---------------------------------------------------------------------------
// LePE attention, fp16 tensor-core end-to-end:
//   qkv GEMM (fp32 in, fp16 out) -> attn (WMMA fp16, fp32 softmax, fp16 out)
//   -> lepe (fp16 RMW) -> proj GEMM (fp16 A, fp32 out + bias).
// B=16, H=W=64, C=384, HEADS=12, hd=32, IDX=0 (vertical strips).
// ---------------------------------------------------------------------------

#define C_DIM   384
#define N_HEADS 12
#define HD      32
#define B_DIM   16
#define NTOK    4096
#define M_TOTAL 65536
#define QKV_N   1152

// Scratch (fp16)
__device__ __half g_qkv_h[(size_t)M_TOTAL * QKV_N];   // (B*N, 3C)
__device__ __half g_comb_h[(size_t)M_TOTAL * C_DIM];  // attn + lepe, (B, N, C)

#define BK    32
#define PAD_H 40   // halves per smem row (80B, multiple of 16B)

// pack 8 floats -> 8 halves (rn) in a uint4
__device__ __forceinline__ uint4 pack8(const float4 f0, const float4 f1) {
    __half2 h0 = __floats2half2_rn(f0.x, f0.y);
    __half2 h1 = __floats2half2_rn(f0.z, f0.w);
    __half2 h2 = __floats2half2_rn(f1.x, f1.y);
    __half2 h3 = __floats2half2_rn(f1.z, f1.w);
    uint4 u;
    u.x = *reinterpret_cast<uint32_t*>(&h0);
    u.y = *reinterpret_cast<uint32_t*>(&h1);
    u.z = *reinterpret_cast<uint32_t*>(&h2);
    u.w = *reinterpret_cast<uint32_t*>(&h3);
    return u;
}

// ---------------------------------------------------------------------------
// GEMM: D[m, n] = sum_k A[m, k] * Bw[n, k]
// A_HALF: A is fp16 (no conversion in loader). OUT_HALF: D is fp16 (no bias);
// else D fp32 with bias. Grid: blockIdx.x = n-block (fast, L2 A-reuse).
// 128x128 tile, BK=32 double-buffered fp16 smem. 8 warps (2m x 4n),
// warp = 4x2 wmma m16n16k16 tiles.
// ---------------------------------------------------------------------------
template <bool A_HALF, bool OUT_HALF>
__global__ __launch_bounds__(256)
void gemm_wmma_kernel(const void* __restrict__ Ax, const float* __restrict__ Bw,
                      const float* __restrict__ bias, void* __restrict__ Dx,
                      int ldD)
{
    __shared__ __half As[2][128 * PAD_H];
    __shared__ __half Bs[2][128 * PAD_H];

    const int tid  = threadIdx.x;
    const int lane = tid & 31;
    const int warp = tid >> 5;
    const int warpM = warp >> 2;       // 0..1  -> 64 rows
    const int warpN = warp & 3;        // 0..3  -> 32 cols
    const int n0 = blockIdx.x * 128;   // n fast
    const int m0 = blockIdx.y * 128;

    const int row  = tid >> 1;         // 0..127
    const int hIdx = tid & 1;          // 16-col group
    const float*  aSrcF = (const float*)Ax + (size_t)(m0 + row) * C_DIM + hIdx * 16;
    const __half* aSrcH = (const __half*)Ax + (size_t)(m0 + row) * C_DIM + hIdx * 16;
    const float*  bSrc  = Bw + (size_t)(n0 + row) * C_DIM + hIdx * 16;
    const int smOff = row * PAD_H + hIdx * 16;   // in halves

    wmma::fragment<wmma::accumulator, 16, 16, 16, float> acc[4][2];
#pragma unroll
    for (int tr = 0; tr < 4; tr++)
#pragma unroll
        for (int tc = 0; tc < 2; tc++)
            wmma::fill_fragment(acc[tr][tc], 0.0f);

    const int NCHUNK = C_DIM / BK;  // 12
    const int aRow = warpM * 64;
    const int bRow = warpN * 32;

    uint4 pA0, pA1, pB0, pB1;
    // prologue: chunk 0
    {
        if (A_HALF) {
            pA0 = *(const uint4*)(aSrcH);
            pA1 = *(const uint4*)(aSrcH + 8);
        } else {
            float4 a0 = *(const float4*)(aSrcF + 0);
            float4 a1 = *(const float4*)(aSrcF + 4);
            float4 a2 = *(const float4*)(aSrcF + 8);
            float4 a3 = *(const float4*)(aSrcF + 12);
            pA0 = pack8(a0, a1); pA1 = pack8(a2, a3);
        }
        float4 b0 = *(const float4*)(bSrc + 0);
        float4 b1 = *(const float4*)(bSrc + 4);
        float4 b2 = *(const float4*)(bSrc + 8);
        float4 b3 = *(const float4*)(bSrc + 12);
        pB0 = pack8(b0, b1); pB1 = pack8(b2, b3);
        *(uint4*)&As[0][smOff]     = pA0;
        *(uint4*)&As[0][smOff + 8] = pA1;
        *(uint4*)&Bs[0][smOff]     = pB0;
        *(uint4*)&Bs[0][smOff + 8] = pB1;
    }
    __syncthreads();

    for (int c = 0; c < NCHUNK; c++) {
        const int buf = c & 1;
        if (c + 1 < NCHUNK) {
            const int k0g = (c + 1) * BK;
            if (A_HALF) {
                pA0 = *(const uint4*)(aSrcH + k0g);
                pA1 = *(const uint4*)(aSrcH + k0g + 8);
            } else {
                float4 a0 = *(const float4*)(aSrcF + k0g + 0);
                float4 a1 = *(const float4*)(aSrcF + k0g + 4);
                float4 a2 = *(const float4*)(aSrcF + k0g + 8);
                float4 a3 = *(const float4*)(aSrcF + k0g + 12);
                pA0 = pack8(a0, a1); pA1 = pack8(a2, a3);
            }
            float4 b0 = *(const float4*)(bSrc + k0g + 0);
            float4 b1 = *(const float4*)(bSrc + k0g + 4);
            float4 b2 = *(const float4*)(bSrc + k0g + 8);
            float4 b3 = *(const float4*)(bSrc + k0g + 12);
            pB0 = pack8(b0, b1); pB1 = pack8(b2, b3);
        }

        const __half* sa = As[buf];
        const __half* sb = Bs[buf];
#pragma unroll
        for (int ks = 0; ks < 2; ks++) {
            const int k0 = ks * 16;
            wmma::fragment<wmma::matrix_a, 16, 16, 16, __half,
                           wmma::row_major> af[4];
            wmma::fragment<wmma::matrix_b, 16, 16, 16, __half,
                           wmma::col_major> bf[2];
#pragma unroll
            for (int tr = 0; tr < 4; tr++)
                wmma::load_matrix_sync(af[tr], sa + (aRow + tr * 16) * PAD_H + k0,
                                       PAD_H);
#pragma unroll
            for (int tc = 0; tc < 2; tc++)
                wmma::load_matrix_sync(bf[tc], sb + (bRow + tc * 16) * PAD_H + k0,
                                       PAD_H);
#pragma unroll
            for (int tr = 0; tr < 4; tr++)
#pragma unroll
                for (int tc = 0; tc < 2; tc++)
                    wmma::mma_sync(acc[tr][tc], af[tr], bf[tc], acc[tr][tc]);
        }

        if (c + 1 < NCHUNK) {
            const int nb = (c + 1) & 1;
            *(uint4*)&As[nb][smOff]     = pA0;
            *(uint4*)&As[nb][smOff + 8] = pA1;
            *(uint4*)&Bs[nb][smOff]     = pB0;
            *(uint4*)&Bs[nb][smOff + 8] = pB1;
            __syncthreads();
        }
    }

    // ---- epilogue ----
    __syncthreads();   // smem free; reuse As as fp32 staging (warp*256 floats)
    float* stage = reinterpret_cast<float*>(&As[0][0]) + warp * 256;

#pragma unroll
    for (int tr = 0; tr < 4; tr++) {
#pragma unroll
        for (int tc = 0; tc < 2; tc++) {
            const int mBase = m0 + warpM * 64 + tr * 16;
            const int nBase = n0 + warpN * 32 + tc * 16;
            wmma::store_matrix_sync(stage, acc[tr][tc], 16, wmma::mem_row_major);
            __syncwarp();
            if (OUT_HALF) {
                __half* Dh = (__half*)Dx;
#pragma unroll
                for (int t = 0; t < 2; t++) {
                    const int idx = t * 32 + lane;  // 0..63 quad index
                    const int r  = idx >> 2;
                    const int c4 = idx & 3;
                    const float* sp = stage + r * 16 + c4 * 4;
                    __half2 h0 = __floats2half2_rn(sp[0], sp[1]);
                    __half2 h1 = __floats2half2_rn(sp[2], sp[3]);
                    uint2 u;
                    u.x = *reinterpret_cast<uint32_t*>(&h0);
                    u.y = *reinterpret_cast<uint32_t*>(&h1);
                    *(uint2*)&Dh[(size_t)(mBase + r) * ldD + nBase + c4 * 4] = u;
                }
            } else {
                float* Df = (float*)Dx;
#pragma unroll
                for (int t = 0; t < 2; t++) {
                    const int idx = t * 32 + lane;
                    const int r  = idx >> 2;
                    const int c4 = idx & 3;
                    float4 v = *(const float4*)(stage + r * 16 + c4 * 4);
                    const float4 b4 = *(const float4*)&bias[nBase + c4 * 4];
                    v.x += b4.x; v.y += b4.y; v.z += b4.z; v.w += b4.w;
                    *(float4*)&Df[(size_t)(mBase + r) * ldD + nBase + c4 * 4] = v;
                }
            }
            __syncwarp();
        }
    }
}

// ---------------------------------------------------------------------------
// Attention via WMMA fp16: one block per (s, head), 128 threads / 4 warps.
// Warp w owns rows [w*16, w*16+16) of the 64x64 score matrix.
// ---------------------------------------------------------------------------
__global__ __launch_bounds__(128) void attn_kernel()
{
    __shared__ __half Qh[64][PAD_H];
    __shared__ __half Kh[64][PAD_H];
    __shared__ __half Vh[64][PAD_H];
    __shared__ float  S[64][68];      // fp32 scores / output staging
    __shared__ __half Ph[64][72];     // fp16 probabilities

    const int g    = blockIdx.x;           // s*12 + head
    const int tid  = threadIdx.x;
    const int warp = tid >> 5, lane = tid & 31;
    const int s    = g / N_HEADS;
    const int head = g - s * N_HEADS;
    const int b    = s >> 6;
    const int w    = s & 63;
    const int cBase = head * HD;

    // gather Q/K/V (fp16): token l -> row b*4096 + l*64 + w of g_qkv_h
    const size_t rowBase = (size_t)(b << 12) + w;
    for (int i = tid; i < 256; i += 128) {
        const int l = i >> 2, grp = i & 3;             // grp: 8-half group
        const size_t off = (rowBase + (size_t)l * 64) * QKV_N + cBase + grp * 8;
        *(uint4*)&Qh[l][grp * 8] = *(const uint4*)&g_qkv_h[off];
        *(uint4*)&Kh[l][grp * 8] = *(const uint4*)&g_qkv_h[off + C_DIM];
        *(uint4*)&Vh[l][grp * 8] = *(const uint4*)&g_qkv_h[off + 2 * C_DIM];
    }
    __syncthreads();

    // S = Q @ K^T  (rows warp*16..+16)
    {
        wmma::fragment<wmma::matrix_a, 16, 16, 16, __half, wmma::row_major> aq[2];
        wmma::load_matrix_sync(aq[0], &Qh[warp * 16][0], PAD_H);
        wmma::load_matrix_sync(aq[1], &Qh[warp * 16][16], PAD_H);
#pragma unroll
        for (int nt = 0; nt < 4; nt++) {
            wmma::fragment<wmma::accumulator, 16, 16, 16, float> accS;
            wmma::fill_fragment(accS, 0.0f);
#pragma unroll
            for (int k0 = 0; k0 < 2; k0++) {
                wmma::fragment<wmma::matrix_b, 16, 16, 16, __half,
                               wmma::col_major> bk;
                wmma::load_matrix_sync(bk, &Kh[nt * 16][k0 * 16], PAD_H);
                wmma::mma_sync(accS, aq[k0], bk, accS);
            }
            wmma::store_matrix_sync(&S[warp * 16][nt * 16], accS, 68,
                                    wmma::mem_row_major);
        }
    }
    __syncwarp();

    // softmax (fp32) on own 16 rows; write P fp16
    const float scale = 0.17677669529663687f;   // 1/sqrt(32)
#pragma unroll
    for (int r = 0; r < 16; r++) {
        const int l = warp * 16 + r;
        float v0 = S[l][lane] * scale, v1 = S[l][lane + 32] * scale;
        float mx = fmaxf(v0, v1);
#pragma unroll
        for (int o = 16; o; o >>= 1) mx = fmaxf(mx, __shfl_xor_sync(0xFFFFFFFFu, mx, o));
        const float e0 = __expf(v0 - mx);
        const float e1 = __expf(v1 - mx);
        float sm = e0 + e1;
#pragma unroll
        for (int o = 16; o; o >>= 1) sm += __shfl_xor_sync(0xFFFFFFFFu, sm, o);
        const float inv = 1.f / sm;
        Ph[l][lane]      = __float2half(e0 * inv);
        Ph[l][lane + 32] = __float2half(e1 * inv);
    }
    __syncwarp();

    // O = P @ V  (rows warp*16..+16), stage fp32 into S, then write fp16
    {
        wmma::fragment<wmma::matrix_a, 16, 16, 16, __half, wmma::row_major> ap[4];
#pragma unroll
        for (int k0 = 0; k0 < 4; k0++)
            wmma::load_matrix_sync(ap[k0], &Ph[warp * 16][k0 * 16], 72);
#pragma unroll
        for (int nt = 0; nt < 2; nt++) {
            wmma::fragment<wmma::accumulator, 16, 16, 16, float> accO;
            wmma::fill_fragment(accO, 0.0f);
#pragma unroll
            for (int k0 = 0; k0 < 4; k0++) {
                wmma::fragment<wmma::matrix_b, 16, 16, 16, __half,
                               wmma::row_major> bv;
                wmma::load_matrix_sync(bv, &Vh[k0 * 16][nt * 16], PAD_H);
                wmma::mma_sync(accO, ap[k0], bv, accO);
            }
            wmma::store_matrix_sync(&S[warp * 16][nt * 16], accO, 68,
                                    wmma::mem_row_major);
        }
    }
    __syncwarp();

    // write fp16 to g_comb_h rows b*4096 + w*64 + l
    __half* dstBase = g_comb_h +
        ((size_t)(b << 12) + (w << 6) + warp * 16) * C_DIM + cBase;
    for (int idx = lane; idx < 128; idx += 32) {   // 16 rows x 8 quad-groups
        const int r = idx >> 3, grp = idx & 7;
        const float* sp = &S[warp * 16 + r][grp * 4];
        __half2 h0 = __floats2half2_rn(sp[0], sp[1]);
        __half2 h1 = __floats2half2_rn(sp[2], sp[3]);
        uint2 u;
        u.x = *reinterpret_cast<uint32_t*>(&h0);
        u.y = *reinterpret_cast<uint32_t*>(&h1);
        *(uint2*)&dstBase[(size_t)r * C_DIM + grp * 4] = u;
    }
}

// ---------------------------------------------------------------------------
// LePE: depthwise 3x3 over x, fp16 += into g_comb_h.
// ---------------------------------------------------------------------------
__global__ __launch_bounds__(C_DIM) void lepe_kernel(
    const float* __restrict__ x, const float* __restrict__ lw,
    const float* __restrict__ lb)
{
    const int n  = blockIdx.x;
    const int c  = threadIdx.x;
    const int b  = n >> 12;
    const int sp = n & 4095;
    const int hh = sp >> 6;
    const int ww = sp & 63;

    float acc = lb[c];
    const float* wc = lw + c * 9;
    const size_t xbase = (size_t)(b << 12) * C_DIM;

#pragma unroll
    for (int dy = -1; dy <= 1; dy++) {
        const int y = hh + dy;
        if (y < 0 || y > 63) continue;
#pragma unroll
        for (int dx = -1; dx <= 1; dx++) {
            const int xx = ww + dx;
            if (xx < 0 || xx > 63) continue;
            acc += x[xbase + (size_t)((y << 6) + xx) * C_DIM + c] *
                   wc[(dy + 1) * 3 + (dx + 1)];
        }
    }
    const size_t oidx = (size_t)n * C_DIM + c;
    const float prev = __half2float(g_comb_h[oidx]);
    g_comb_h[oidx] = __float2half(prev + acc);
}

// ---------------------------------------------------------------------------
extern "C" void kernel_launch(void* const* d_in, const int* in_sizes, int n_in,
                              void* d_out, int out_size)
{
    const float* x      = (const float*)d_in[0];
    const float* qkv_w  = (const float*)d_in[1];
    const float* proj_w = (const float*)d_in[2];
    const float* proj_b = (const float*)d_in[3];
    const float* lepe_w = (const float*)d_in[4];
    const float* lepe_b = (const float*)d_in[5];
    float* out = (float*)d_out;
    (void)in_sizes; (void)n_in; (void)out_size;

    void* qkv_h; cudaGetSymbolAddress(&qkv_h, g_qkv_h);
    void* comb_h; cudaGetSymbolAddress(&comb_h, g_comb_h);

    // qkv: (65536 x 384)f32 @ (1152 x 384)^T -> fp16 (65536 x 1152); n-fast
    dim3 g_qkv_grid(QKV_N / 128, M_TOTAL / 128);   // (9, 512)
    gemm_wmma_kernel<false, true><<<g_qkv_grid, 256>>>(
        x, qkv_w, nullptr, qkv_h, QKV_N);

    attn_kernel<<<B_DIM * 64 * N_HEADS, 128>>>();   // 12288 blocks

    lepe_kernel<<<B_DIM * NTOK, C_DIM>>>(x, lepe_w, lepe_b);

    // proj: (65536 x 384)fp16 @ (384 x 384)^T + b -> fp32 out; n-fast
    dim3 g_proj_grid(C_DIM / 128, M_TOTAL / 128);  // (3, 512)
    gemm_wmma_kernel<true, false><<<g_proj_grid, 256>>>(
        comb_h, proj_w, proj_b, out, C_DIM);
}

// round 13
// speedup vs baseline: 2.5815x; 1.2366x over previous
#include <cuda_runtime.h>
#include <cuda_fp16.h>
#include <mma.h>
#include <cstdint>

using namespace nvcuda;

// ---------------------------------------------------------------------------
// LePE attention, fp16 tensor-core end-to-end (R13):
//   cvt x/weights -> fp16 | qkv GEMM (cp.async, 64x64 warp tiles, fp16 out)
//   -> attn (WMMA fp16) -> lepe (register-rotation, fp16 RMW)
//   -> proj GEMM (fp16 in, fp32 out + bias).
// B=16, H=W=64, C=384, HEADS=12, hd=32, IDX=0 (vertical strips).
// ---------------------------------------------------------------------------

#define C_DIM   384
#define N_HEADS 12
#define HD      32
#define B_DIM   16
#define NTOK    4096
#define M_TOTAL 65536
#define QKV_N   1152

// Scratch (fp16)
__device__ __half g_x_h[(size_t)M_TOTAL * C_DIM];     // x in fp16
__device__ __half g_qkvw_h[(size_t)QKV_N * C_DIM];    // qkv_w fp16
__device__ __half g_projw_h[(size_t)C_DIM * C_DIM];   // proj_w fp16
__device__ __half g_qkv_h[(size_t)M_TOTAL * QKV_N];   // (B*N, 3C)
__device__ __half g_comb_h[(size_t)M_TOTAL * C_DIM];  // attn + lepe

#define BK    32
#define PAD_H 40   // halves per smem row (80B)

__device__ __forceinline__ uint4 pack8(const float4 f0, const float4 f1) {
    __half2 h0 = __floats2half2_rn(f0.x, f0.y);
    __half2 h1 = __floats2half2_rn(f0.z, f0.w);
    __half2 h2 = __floats2half2_rn(f1.x, f1.y);
    __half2 h3 = __floats2half2_rn(f1.z, f1.w);
    uint4 u;
    u.x = *reinterpret_cast<uint32_t*>(&h0);
    u.y = *reinterpret_cast<uint32_t*>(&h1);
    u.z = *reinterpret_cast<uint32_t*>(&h2);
    u.w = *reinterpret_cast<uint32_t*>(&h3);
    return u;
}

// ---------------------------------------------------------------------------
// fp32 -> fp16 conversion (n multiple of 8)
// ---------------------------------------------------------------------------
__global__ __launch_bounds__(256) void cvt_f32_f16_kernel(
    const float* __restrict__ src, __half* __restrict__ dst, int n)
{
    const int i = (blockIdx.x * 256 + threadIdx.x) * 8;
    if (i < n) {
        float4 a = *(const float4*)(src + i);
        float4 b = *(const float4*)(src + i + 4);
        *(uint4*)(dst + i) = pack8(a, b);
    }
}

// ---------------------------------------------------------------------------
// GEMM (all-fp16 inputs): D[m,n] = sum_k A[m,k] * Bw[n,k]
// 128 threads / 4 warps (2m x 2n), warp tile 64x64 (4x4 m16n16k16).
// 128x128 CTA tile, BK=32, cp.async double-buffered.
// Grid: blockIdx.x = n-block (fast, L2 A-reuse).
// OUT_HALF: D fp16, no bias. else: D fp32 + bias.
// ---------------------------------------------------------------------------
template <bool OUT_HALF>
__global__ __launch_bounds__(128)
void gemm_h_kernel(const __half* __restrict__ A, const __half* __restrict__ Bw,
                   const float* __restrict__ bias, void* __restrict__ Dx,
                   int ldD)
{
    __shared__ __half As[2][128 * PAD_H];
    __shared__ __half Bs[2][128 * PAD_H];

    const int tid  = threadIdx.x;
    const int lane = tid & 31;
    const int warp = tid >> 5;         // 0..3
    const int warpM = warp >> 1;       // 0..1 -> 64 rows
    const int warpN = warp & 1;        // 0..1 -> 64 cols
    const int n0 = blockIdx.x * 128;   // n fast
    const int m0 = blockIdx.y * 128;

    // loader: thread t -> row t (A and B), full 32-half chunk row
    const __half* aSrc = A + (size_t)(m0 + tid) * C_DIM;
    const __half* bSrc = Bw + (size_t)(n0 + tid) * C_DIM;
    uint32_t smA[2], smB[2];
#pragma unroll
    for (int bfi = 0; bfi < 2; bfi++) {
        smA[bfi] = (uint32_t)__cvta_generic_to_shared(&As[bfi][tid * PAD_H]);
        smB[bfi] = (uint32_t)__cvta_generic_to_shared(&Bs[bfi][tid * PAD_H]);
    }

    wmma::fragment<wmma::accumulator, 16, 16, 16, float> acc[4][4];
#pragma unroll
    for (int tr = 0; tr < 4; tr++)
#pragma unroll
        for (int tc = 0; tc < 4; tc++)
            wmma::fill_fragment(acc[tr][tc], 0.0f);

    const int NCHUNK = C_DIM / BK;  // 12

    // prologue: issue chunk 0 into buf 0
#pragma unroll
    for (int q = 0; q < 4; q++) {
        asm volatile("cp.async.cg.shared.global [%0], [%1], 16;"
                     :: "r"(smA[0] + q * 16), "l"(aSrc + q * 8) : "memory");
        asm volatile("cp.async.cg.shared.global [%0], [%1], 16;"
                     :: "r"(smB[0] + q * 16), "l"(bSrc + q * 8) : "memory");
    }
    asm volatile("cp.async.commit_group;" ::: "memory");

    for (int c = 0; c < NCHUNK; c++) {
        asm volatile("cp.async.wait_group 0;" ::: "memory");
        __syncthreads();   // chunk c ready; all warps done with chunk c-1

        if (c + 1 < NCHUNK) {
            const int nb = (c + 1) & 1;
            const __half* aN = aSrc + (c + 1) * BK;
            const __half* bN = bSrc + (c + 1) * BK;
#pragma unroll
            for (int q = 0; q < 4; q++) {
                asm volatile("cp.async.cg.shared.global [%0], [%1], 16;"
                             :: "r"(smA[nb] + q * 16), "l"(aN + q * 8) : "memory");
                asm volatile("cp.async.cg.shared.global [%0], [%1], 16;"
                             :: "r"(smB[nb] + q * 16), "l"(bN + q * 8) : "memory");
            }
            asm volatile("cp.async.commit_group;" ::: "memory");
        }

        const __half* sa = As[c & 1];
        const __half* sb = Bs[c & 1];
#pragma unroll
        for (int ks = 0; ks < 2; ks++) {
            const int k0 = ks * 16;
            wmma::fragment<wmma::matrix_a, 16, 16, 16, __half,
                           wmma::row_major> af[4];
#pragma unroll
            for (int tr = 0; tr < 4; tr++)
                wmma::load_matrix_sync(af[tr],
                    sa + (warpM * 64 + tr * 16) * PAD_H + k0, PAD_H);
#pragma unroll
            for (int tc = 0; tc < 4; tc++) {
                wmma::fragment<wmma::matrix_b, 16, 16, 16, __half,
                               wmma::col_major> bf;
                wmma::load_matrix_sync(bf,
                    sb + (warpN * 64 + tc * 16) * PAD_H + k0, PAD_H);
#pragma unroll
                for (int tr = 0; tr < 4; tr++)
                    wmma::mma_sync(acc[tr][tc], af[tr], bf, acc[tr][tc]);
            }
        }
    }
    __syncthreads();

    // epilogue: per-warp 16x16 staging in As[0] region
    float* stage = reinterpret_cast<float*>(&As[0][0]) + warp * 256;
#pragma unroll
    for (int tr = 0; tr < 4; tr++) {
#pragma unroll
        for (int tc = 0; tc < 4; tc++) {
            const int mBase = m0 + warpM * 64 + tr * 16;
            const int nBase = n0 + warpN * 64 + tc * 16;
            wmma::store_matrix_sync(stage, acc[tr][tc], 16, wmma::mem_row_major);
            __syncwarp();
            if (OUT_HALF) {
                __half* Dh = (__half*)Dx;
#pragma unroll
                for (int t = 0; t < 2; t++) {
                    const int idx = t * 32 + lane;   // quad 0..63
                    const int r  = idx >> 2;
                    const int c4 = idx & 3;
                    const float* sp = stage + r * 16 + c4 * 4;
                    __half2 h0 = __floats2half2_rn(sp[0], sp[1]);
                    __half2 h1 = __floats2half2_rn(sp[2], sp[3]);
                    uint2 u;
                    u.x = *reinterpret_cast<uint32_t*>(&h0);
                    u.y = *reinterpret_cast<uint32_t*>(&h1);
                    *(uint2*)&Dh[(size_t)(mBase + r) * ldD + nBase + c4 * 4] = u;
                }
            } else {
                float* Df = (float*)Dx;
#pragma unroll
                for (int t = 0; t < 2; t++) {
                    const int idx = t * 32 + lane;
                    const int r  = idx >> 2;
                    const int c4 = idx & 3;
                    float4 v = *(const float4*)(stage + r * 16 + c4 * 4);
                    const float4 b4 = *(const float4*)&bias[nBase + c4 * 4];
                    v.x += b4.x; v.y += b4.y; v.z += b4.z; v.w += b4.w;
                    *(float4*)&Df[(size_t)(mBase + r) * ldD + nBase + c4 * 4] = v;
                }
            }
            __syncwarp();
        }
    }
}

// ---------------------------------------------------------------------------
// Attention via WMMA fp16: one block per (s, head), 128 threads / 4 warps.
// ---------------------------------------------------------------------------
__global__ __launch_bounds__(128) void attn_kernel()
{
    __shared__ __half Qh[64][PAD_H];
    __shared__ __half Kh[64][PAD_H];
    __shared__ __half Vh[64][PAD_H];
    __shared__ float  S[64][68];
    __shared__ __half Ph[64][72];

    const int g    = blockIdx.x;
    const int tid  = threadIdx.x;
    const int warp = tid >> 5, lane = tid & 31;
    const int s    = g / N_HEADS;
    const int head = g - s * N_HEADS;
    const int b    = s >> 6;
    const int w    = s & 63;
    const int cBase = head * HD;

    const size_t rowBase = (size_t)(b << 12) + w;
    for (int i = tid; i < 256; i += 128) {
        const int l = i >> 2, grp = i & 3;
        const size_t off = (rowBase + (size_t)l * 64) * QKV_N + cBase + grp * 8;
        *(uint4*)&Qh[l][grp * 8] = *(const uint4*)&g_qkv_h[off];
        *(uint4*)&Kh[l][grp * 8] = *(const uint4*)&g_qkv_h[off + C_DIM];
        *(uint4*)&Vh[l][grp * 8] = *(const uint4*)&g_qkv_h[off + 2 * C_DIM];
    }
    __syncthreads();

    {
        wmma::fragment<wmma::matrix_a, 16, 16, 16, __half, wmma::row_major> aq[2];
        wmma::load_matrix_sync(aq[0], &Qh[warp * 16][0], PAD_H);
        wmma::load_matrix_sync(aq[1], &Qh[warp * 16][16], PAD_H);
#pragma unroll
        for (int nt = 0; nt < 4; nt++) {
            wmma::fragment<wmma::accumulator, 16, 16, 16, float> accS;
            wmma::fill_fragment(accS, 0.0f);
#pragma unroll
            for (int k0 = 0; k0 < 2; k0++) {
                wmma::fragment<wmma::matrix_b, 16, 16, 16, __half,
                               wmma::col_major> bk;
                wmma::load_matrix_sync(bk, &Kh[nt * 16][k0 * 16], PAD_H);
                wmma::mma_sync(accS, aq[k0], bk, accS);
            }
            wmma::store_matrix_sync(&S[warp * 16][nt * 16], accS, 68,
                                    wmma::mem_row_major);
        }
    }
    __syncwarp();

    const float scale = 0.17677669529663687f;
#pragma unroll
    for (int r = 0; r < 16; r++) {
        const int l = warp * 16 + r;
        float v0 = S[l][lane] * scale, v1 = S[l][lane + 32] * scale;
        float mx = fmaxf(v0, v1);
#pragma unroll
        for (int o = 16; o; o >>= 1) mx = fmaxf(mx, __shfl_xor_sync(0xFFFFFFFFu, mx, o));
        const float e0 = __expf(v0 - mx);
        const float e1 = __expf(v1 - mx);
        float sm = e0 + e1;
#pragma unroll
        for (int o = 16; o; o >>= 1) sm += __shfl_xor_sync(0xFFFFFFFFu, sm, o);
        const float inv = 1.f / sm;
        Ph[l][lane]      = __float2half(e0 * inv);
        Ph[l][lane + 32] = __float2half(e1 * inv);
    }
    __syncwarp();

    {
        wmma::fragment<wmma::matrix_a, 16, 16, 16, __half, wmma::row_major> ap[4];
#pragma unroll
        for (int k0 = 0; k0 < 4; k0++)
            wmma::load_matrix_sync(ap[k0], &Ph[warp * 16][k0 * 16], 72);
#pragma unroll
        for (int nt = 0; nt < 2; nt++) {
            wmma::fragment<wmma::accumulator, 16, 16, 16, float> accO;
            wmma::fill_fragment(accO, 0.0f);
#pragma unroll
            for (int k0 = 0; k0 < 4; k0++) {
                wmma::fragment<wmma::matrix_b, 16, 16, 16, __half,
                               wmma::row_major> bv;
                wmma::load_matrix_sync(bv, &Vh[k0 * 16][nt * 16], PAD_H);
                wmma::mma_sync(accO, ap[k0], bv, accO);
            }
            wmma::store_matrix_sync(&S[warp * 16][nt * 16], accO, 68,
                                    wmma::mem_row_major);
        }
    }
    __syncwarp();

    __half* dstBase = g_comb_h +
        ((size_t)(b << 12) + (w << 6) + warp * 16) * C_DIM + cBase;
    for (int idx = lane; idx < 128; idx += 32) {
        const int r = idx >> 3, grp = idx & 7;
        const float* sp = &S[warp * 16 + r][grp * 4];
        __half2 h0 = __floats2half2_rn(sp[0], sp[1]);
        __half2 h1 = __floats2half2_rn(sp[2], sp[3]);
        uint2 u;
        u.x = *reinterpret_cast<uint32_t*>(&h0);
        u.y = *reinterpret_cast<uint32_t*>(&h1);
        *(uint2*)&dstBase[(size_t)r * C_DIM + grp * 4] = u;
    }
}

// ---------------------------------------------------------------------------
// LePE: depthwise 3x3, register-rotation along the row. One block per
// (b, hh); 384 threads = channels. fp16 += into g_comb_h.
// ---------------------------------------------------------------------------
__global__ __launch_bounds__(C_DIM) void lepe_kernel(
    const float* __restrict__ x, const float* __restrict__ lw,
    const float* __restrict__ lb)
{
    const int blk = blockIdx.x;       // b*64 + hh
    const int c   = threadIdx.x;
    const int b   = blk >> 6;
    const int hh  = blk & 63;

    float w9[9];
#pragma unroll
    for (int k = 0; k < 9; k++) w9[k] = lw[c * 9 + k];
    const float bch = lb[c];

    const float* xrow[3];
    bool valid[3];
#pragma unroll
    for (int j = 0; j < 3; j++) {
        const int y = hh - 1 + j;
        valid[j] = (y >= 0 && y < 64);
        xrow[j] = x + (size_t)((b << 12) + (y << 6)) * C_DIM + c;
    }

    float xm1[3], x0[3], xp1[3];
#pragma unroll
    for (int j = 0; j < 3; j++) {
        xm1[j] = 0.f;
        x0[j]  = valid[j] ? xrow[j][0] : 0.f;
        xp1[j] = valid[j] ? xrow[j][C_DIM] : 0.f;
    }

    __half* crow = g_comb_h + (size_t)((b << 12) + (hh << 6)) * C_DIM + c;

    for (int ww = 0; ww < 64; ww++) {
        float acc = bch;
#pragma unroll
        for (int j = 0; j < 3; j++)
            acc += xm1[j] * w9[j * 3 + 0] + x0[j] * w9[j * 3 + 1] +
                   xp1[j] * w9[j * 3 + 2];
        const size_t oi = (size_t)ww * C_DIM;
        crow[oi] = __float2half(__half2float(crow[oi]) + acc);

        // rotate window
#pragma unroll
        for (int j = 0; j < 3; j++) {
            xm1[j] = x0[j];
            x0[j]  = xp1[j];
            const int nxt = ww + 2;
            xp1[j] = (nxt < 64 && valid[j])
                     ? xrow[j][(size_t)nxt * C_DIM] : 0.f;
        }
    }
}

// ---------------------------------------------------------------------------
extern "C" void kernel_launch(void* const* d_in, const int* in_sizes, int n_in,
                              void* d_out, int out_size)
{
    const float* x      = (const float*)d_in[0];
    const float* qkv_w  = (const float*)d_in[1];
    const float* proj_w = (const float*)d_in[2];
    const float* proj_b = (const float*)d_in[3];
    const float* lepe_w = (const float*)d_in[4];
    const float* lepe_b = (const float*)d_in[5];
    float* out = (float*)d_out;
    (void)in_sizes; (void)n_in; (void)out_size;

    void *x_h, *qkvw_h, *projw_h, *qkv_h, *comb_h;
    cudaGetSymbolAddress(&x_h, g_x_h);
    cudaGetSymbolAddress(&qkvw_h, g_qkvw_h);
    cudaGetSymbolAddress(&projw_h, g_projw_h);
    cudaGetSymbolAddress(&qkv_h, g_qkv_h);
    cudaGetSymbolAddress(&comb_h, g_comb_h);

    // fp32 -> fp16 conversions
    const int nx = M_TOTAL * C_DIM;          // 25165824
    const int nq = QKV_N * C_DIM;            // 442368
    const int np = C_DIM * C_DIM;            // 147456
    cvt_f32_f16_kernel<<<nx / 2048, 256>>>(x, (__half*)x_h, nx);
    cvt_f32_f16_kernel<<<(nq + 2047) / 2048, 256>>>(qkv_w, (__half*)qkvw_h, nq);
    cvt_f32_f16_kernel<<<(np + 2047) / 2048, 256>>>(proj_w, (__half*)projw_h, np);

    // qkv: (65536 x 384)h @ (1152 x 384)^T h -> fp16; n-fast grid
    dim3 g_qkv_grid(QKV_N / 128, M_TOTAL / 128);   // (9, 512)
    gemm_h_kernel<true><<<g_qkv_grid, 128>>>(
        (const __half*)x_h, (const __half*)qkvw_h, nullptr, qkv_h, QKV_N);

    attn_kernel<<<B_DIM * 64 * N_HEADS, 128>>>();   // 12288 blocks

    lepe_kernel<<<B_DIM * 64, C_DIM>>>(x, lepe_w, lepe_b);  // 1024 blocks

    // proj: (65536 x 384)h @ (384 x 384)^T h + bias -> fp32 out; n-fast grid
    dim3 g_proj_grid(C_DIM / 128, M_TOTAL / 128);  // (3, 512)
    gemm_h_kernel<false><<<g_proj_grid, 128>>>(
        (const __half*)comb_h, (const __half*)projw_h, proj_b, out, C_DIM);
}

// round 15
// speedup vs baseline: 3.1874x; 1.2347x over previous
#include <cuda_runtime.h>
#include <cuda_fp16.h>
#include <mma.h>
#include <cstdint>

using namespace nvcuda;

// ---------------------------------------------------------------------------
// LePE attention, fp16 tensor-core end-to-end (R15 = R14 with loader-stride
// fix: NT was 2x the real thread count, leaving smem rows unloaded -> NaN):
//   GEMM CTA tile 128m x 192n (6 warps, 64x64 warp tiles) to cut L2 A-traffic.
// B=16, H=W=64, C=384, HEADS=12, hd=32, IDX=0 (vertical strips).
// ---------------------------------------------------------------------------

#define C_DIM   384
#define N_HEADS 12
#define HD      32
#define B_DIM   16
#define NTOK    4096
#define M_TOTAL 65536
#define QKV_N   1152

// Scratch (fp16)
__device__ __half g_x_h[(size_t)M_TOTAL * C_DIM];
__device__ __half g_qkvw_h[(size_t)QKV_N * C_DIM];
__device__ __half g_projw_h[(size_t)C_DIM * C_DIM];
__device__ __half g_qkv_h[(size_t)M_TOTAL * QKV_N];
__device__ __half g_comb_h[(size_t)M_TOTAL * C_DIM];

#define BK    32
#define PAD_H 40   // halves per smem row (80B)

__device__ __forceinline__ uint4 pack8(const float4 f0, const float4 f1) {
    __half2 h0 = __floats2half2_rn(f0.x, f0.y);
    __half2 h1 = __floats2half2_rn(f0.z, f0.w);
    __half2 h2 = __floats2half2_rn(f1.x, f1.y);
    __half2 h3 = __floats2half2_rn(f1.z, f1.w);
    uint4 u;
    u.x = *reinterpret_cast<uint32_t*>(&h0);
    u.y = *reinterpret_cast<uint32_t*>(&h1);
    u.z = *reinterpret_cast<uint32_t*>(&h2);
    u.w = *reinterpret_cast<uint32_t*>(&h3);
    return u;
}

__global__ __launch_bounds__(256) void cvt_f32_f16_kernel(
    const float* __restrict__ src, __half* __restrict__ dst, int n)
{
    const int i = (blockIdx.x * 256 + threadIdx.x) * 8;
    if (i < n) {
        float4 a = *(const float4*)(src + i);
        float4 b = *(const float4*)(src + i + 4);
        *(uint4*)(dst + i) = pack8(a, b);
    }
}

// ---------------------------------------------------------------------------
// GEMM (fp16 in): D[m,n] = sum_k A[m,k] * Bw[n,k]
// CTA tile 128m x (64*NWN)n, 2*NWN warps (2m x NWNn), warp tile 64x64
// (4x4 m16n16k16). BK=32 double-buffered cp.async.
// Grid: blockIdx.x = n-block (fast, L2 A-reuse), blockIdx.y = m-block.
// OUT_HALF: D fp16 no bias; else D fp32 + bias.
// ---------------------------------------------------------------------------
template <int NWN, bool OUT_HALF>
__global__ __launch_bounds__(32 * 2 * NWN)
void gemm_h_kernel(const __half* __restrict__ A, const __half* __restrict__ Bw,
                   const float* __restrict__ bias, void* __restrict__ Dx,
                   int ldD)
{
    constexpr int NT      = 32 * 2 * NWN;     // threads (FIXED: was 64*2*NWN)
    constexpr int N_TILE  = 64 * NWN;
    constexpr int A_UNITS = 128 * 4;          // 16B units per A chunk
    constexpr int B_UNITS = N_TILE * 4;

    __shared__ __half As[2][128 * PAD_H];
    __shared__ __half Bs[2][N_TILE * PAD_H];

    const int tid  = threadIdx.x;
    const int lane = tid & 31;
    const int warp = tid >> 5;                // 0 .. 2*NWN-1
    const int warpM = warp / NWN;             // 0..1
    const int warpN = warp % NWN;             // 0..NWN-1
    const int n0 = blockIdx.x * N_TILE;       // n fast
    const int m0 = blockIdx.y * 128;

    const __half* aTile = A + (size_t)m0 * C_DIM;
    const __half* bTile = Bw + (size_t)n0 * C_DIM;

    uint32_t smA[2], smB[2];
#pragma unroll
    for (int bfi = 0; bfi < 2; bfi++) {
        smA[bfi] = (uint32_t)__cvta_generic_to_shared(&As[bfi][0]);
        smB[bfi] = (uint32_t)__cvta_generic_to_shared(&Bs[bfi][0]);
    }

    wmma::fragment<wmma::accumulator, 16, 16, 16, float> acc[4][4];
#pragma unroll
    for (int tr = 0; tr < 4; tr++)
#pragma unroll
        for (int tc = 0; tc < 4; tc++)
            wmma::fill_fragment(acc[tr][tc], 0.0f);

    const int NCHUNK = C_DIM / BK;  // 12

    auto issue_chunk = [&](int c, int bfi) {
        const int k0g = c * BK;
#pragma unroll
        for (int u = tid; u < A_UNITS; u += NT) {
            const int row = u >> 2, q = u & 3;
            asm volatile("cp.async.cg.shared.global [%0], [%1], 16;"
                :: "r"(smA[bfi] + (row * PAD_H + q * 8) * 2),
                   "l"(aTile + (size_t)row * C_DIM + k0g + q * 8) : "memory");
        }
#pragma unroll
        for (int u = tid; u < B_UNITS; u += NT) {
            const int row = u >> 2, q = u & 3;
            asm volatile("cp.async.cg.shared.global [%0], [%1], 16;"
                :: "r"(smB[bfi] + (row * PAD_H + q * 8) * 2),
                   "l"(bTile + (size_t)row * C_DIM + k0g + q * 8) : "memory");
        }
        asm volatile("cp.async.commit_group;" ::: "memory");
    };

    issue_chunk(0, 0);

    for (int c = 0; c < NCHUNK; c++) {
        asm volatile("cp.async.wait_group 0;" ::: "memory");
        __syncthreads();

        if (c + 1 < NCHUNK) issue_chunk(c + 1, (c + 1) & 1);

        const __half* sa = As[c & 1];
        const __half* sb = Bs[c & 1];
#pragma unroll
        for (int ks = 0; ks < 2; ks++) {
            const int k0 = ks * 16;
            wmma::fragment<wmma::matrix_a, 16, 16, 16, __half,
                           wmma::row_major> af[4];
#pragma unroll
            for (int tr = 0; tr < 4; tr++)
                wmma::load_matrix_sync(af[tr],
                    sa + (warpM * 64 + tr * 16) * PAD_H + k0, PAD_H);
#pragma unroll
            for (int tc = 0; tc < 4; tc++) {
                wmma::fragment<wmma::matrix_b, 16, 16, 16, __half,
                               wmma::col_major> bf;
                wmma::load_matrix_sync(bf,
                    sb + (warpN * 64 + tc * 16) * PAD_H + k0, PAD_H);
#pragma unroll
                for (int tr = 0; tr < 4; tr++)
                    wmma::mma_sync(acc[tr][tc], af[tr], bf, acc[tr][tc]);
            }
        }
    }
    __syncthreads();

    // epilogue: per-warp 16x16 fp32 staging in As region
    float* stage = reinterpret_cast<float*>(&As[0][0]) + warp * 256;
#pragma unroll
    for (int tr = 0; tr < 4; tr++) {
#pragma unroll
        for (int tc = 0; tc < 4; tc++) {
            const int mBase = m0 + warpM * 64 + tr * 16;
            const int nBase = n0 + warpN * 64 + tc * 16;
            wmma::store_matrix_sync(stage, acc[tr][tc], 16, wmma::mem_row_major);
            __syncwarp();
            if (OUT_HALF) {
                __half* Dh = (__half*)Dx;
#pragma unroll
                for (int t = 0; t < 2; t++) {
                    const int idx = t * 32 + lane;
                    const int r  = idx >> 2;
                    const int c4 = idx & 3;
                    const float* sp = stage + r * 16 + c4 * 4;
                    __half2 h0 = __floats2half2_rn(sp[0], sp[1]);
                    __half2 h1 = __floats2half2_rn(sp[2], sp[3]);
                    uint2 u;
                    u.x = *reinterpret_cast<uint32_t*>(&h0);
                    u.y = *reinterpret_cast<uint32_t*>(&h1);
                    *(uint2*)&Dh[(size_t)(mBase + r) * ldD + nBase + c4 * 4] = u;
                }
            } else {
                float* Df = (float*)Dx;
#pragma unroll
                for (int t = 0; t < 2; t++) {
                    const int idx = t * 32 + lane;
                    const int r  = idx >> 2;
                    const int c4 = idx & 3;
                    float4 v = *(const float4*)(stage + r * 16 + c4 * 4);
                    const float4 b4 = *(const float4*)&bias[nBase + c4 * 4];
                    v.x += b4.x; v.y += b4.y; v.z += b4.z; v.w += b4.w;
                    *(float4*)&Df[(size_t)(mBase + r) * ldD + nBase + c4 * 4] = v;
                }
            }
            __syncwarp();
        }
    }
}

// ---------------------------------------------------------------------------
// Attention via WMMA fp16: one block per (s, head), 128 threads / 4 warps.
// ---------------------------------------------------------------------------
__global__ __launch_bounds__(128) void attn_kernel()
{
    __shared__ __half Qh[64][PAD_H];
    __shared__ __half Kh[64][PAD_H];
    __shared__ __half Vh[64][PAD_H];
    __shared__ float  S[64][68];
    __shared__ __half Ph[64][72];

    const int g    = blockIdx.x;
    const int tid  = threadIdx.x;
    const int warp = tid >> 5, lane = tid & 31;
    const int s    = g / N_HEADS;
    const int head = g - s * N_HEADS;
    const int b    = s >> 6;
    const int w    = s & 63;
    const int cBase = head * HD;

    const size_t rowBase = (size_t)(b << 12) + w;
    for (int i = tid; i < 256; i += 128) {
        const int l = i >> 2, grp = i & 3;
        const size_t off = (rowBase + (size_t)l * 64) * QKV_N + cBase + grp * 8;
        *(uint4*)&Qh[l][grp * 8] = *(const uint4*)&g_qkv_h[off];
        *(uint4*)&Kh[l][grp * 8] = *(const uint4*)&g_qkv_h[off + C_DIM];
        *(uint4*)&Vh[l][grp * 8] = *(const uint4*)&g_qkv_h[off + 2 * C_DIM];
    }
    __syncthreads();

    {
        wmma::fragment<wmma::matrix_a, 16, 16, 16, __half, wmma::row_major> aq[2];
        wmma::load_matrix_sync(aq[0], &Qh[warp * 16][0], PAD_H);
        wmma::load_matrix_sync(aq[1], &Qh[warp * 16][16], PAD_H);
#pragma unroll
        for (int nt = 0; nt < 4; nt++) {
            wmma::fragment<wmma::accumulator, 16, 16, 16, float> accS;
            wmma::fill_fragment(accS, 0.0f);
#pragma unroll
            for (int k0 = 0; k0 < 2; k0++) {
                wmma::fragment<wmma::matrix_b, 16, 16, 16, __half,
                               wmma::col_major> bk;
                wmma::load_matrix_sync(bk, &Kh[nt * 16][k0 * 16], PAD_H);
                wmma::mma_sync(accS, aq[k0], bk, accS);
            }
            wmma::store_matrix_sync(&S[warp * 16][nt * 16], accS, 68,
                                    wmma::mem_row_major);
        }
    }
    __syncwarp();

    const float scale = 0.17677669529663687f;
#pragma unroll
    for (int r = 0; r < 16; r++) {
        const int l = warp * 16 + r;
        float v0 = S[l][lane] * scale, v1 = S[l][lane + 32] * scale;
        float mx = fmaxf(v0, v1);
#pragma unroll
        for (int o = 16; o; o >>= 1) mx = fmaxf(mx, __shfl_xor_sync(0xFFFFFFFFu, mx, o));
        const float e0 = __expf(v0 - mx);
        const float e1 = __expf(v1 - mx);
        float sm = e0 + e1;
#pragma unroll
        for (int o = 16; o; o >>= 1) sm += __shfl_xor_sync(0xFFFFFFFFu, sm, o);
        const float inv = 1.f / sm;
        Ph[l][lane]      = __float2half(e0 * inv);
        Ph[l][lane + 32] = __float2half(e1 * inv);
    }
    __syncwarp();

    {
        wmma::fragment<wmma::matrix_a, 16, 16, 16, __half, wmma::row_major> ap[4];
#pragma unroll
        for (int k0 = 0; k0 < 4; k0++)
            wmma::load_matrix_sync(ap[k0], &Ph[warp * 16][k0 * 16], 72);
#pragma unroll
        for (int nt = 0; nt < 2; nt++) {
            wmma::fragment<wmma::accumulator, 16, 16, 16, float> accO;
            wmma::fill_fragment(accO, 0.0f);
#pragma unroll
            for (int k0 = 0; k0 < 4; k0++) {
                wmma::fragment<wmma::matrix_b, 16, 16, 16, __half,
                               wmma::row_major> bv;
                wmma::load_matrix_sync(bv, &Vh[k0 * 16][nt * 16], PAD_H);
                wmma::mma_sync(accO, ap[k0], bv, accO);
            }
            wmma::store_matrix_sync(&S[warp * 16][nt * 16], accO, 68,
                                    wmma::mem_row_major);
        }
    }
    __syncwarp();

    __half* dstBase = g_comb_h +
        ((size_t)(b << 12) + (w << 6) + warp * 16) * C_DIM + cBase;
    for (int idx = lane; idx < 128; idx += 32) {
        const int r = idx >> 3, grp = idx & 7;
        const float* sp = &S[warp * 16 + r][grp * 4];
        __half2 h0 = __floats2half2_rn(sp[0], sp[1]);
        __half2 h1 = __floats2half2_rn(sp[2], sp[3]);
        uint2 u;
        u.x = *reinterpret_cast<uint32_t*>(&h0);
        u.y = *reinterpret_cast<uint32_t*>(&h1);
        *(uint2*)&dstBase[(size_t)r * C_DIM + grp * 4] = u;
    }
}

// ---------------------------------------------------------------------------
// LePE: depthwise 3x3, register-rotation along the row. One block per
// (b, hh); 384 threads = channels. fp16 += into g_comb_h.
// ---------------------------------------------------------------------------
__global__ __launch_bounds__(C_DIM) void lepe_kernel(
    const float* __restrict__ x, const float* __restrict__ lw,
    const float* __restrict__ lb)
{
    const int blk = blockIdx.x;       // b*64 + hh
    const int c   = threadIdx.x;
    const int b   = blk >> 6;
    const int hh  = blk & 63;

    float w9[9];
#pragma unroll
    for (int k = 0; k < 9; k++) w9[k] = lw[c * 9 + k];
    const float bch = lb[c];

    const float* xrow[3];
    bool valid[3];
#pragma unroll
    for (int j = 0; j < 3; j++) {
        const int y = hh - 1 + j;
        valid[j] = (y >= 0 && y < 64);
        xrow[j] = x + (size_t)((b << 12) + (y << 6)) * C_DIM + c;
    }

    float xm1[3], x0[3], xp1[3];
#pragma unroll
    for (int j = 0; j < 3; j++) {
        xm1[j] = 0.f;
        x0[j]  = valid[j] ? xrow[j][0] : 0.f;
        xp1[j] = valid[j] ? xrow[j][C_DIM] : 0.f;
    }

    __half* crow = g_comb_h + (size_t)((b << 12) + (hh << 6)) * C_DIM + c;

    for (int ww = 0; ww < 64; ww++) {
        float acc = bch;
#pragma unroll
        for (int j = 0; j < 3; j++)
            acc += xm1[j] * w9[j * 3 + 0] + x0[j] * w9[j * 3 + 1] +
                   xp1[j] * w9[j * 3 + 2];
        const size_t oi = (size_t)ww * C_DIM;
        crow[oi] = __float2half(__half2float(crow[oi]) + acc);

#pragma unroll
        for (int j = 0; j < 3; j++) {
            xm1[j] = x0[j];
            x0[j]  = xp1[j];
            const int nxt = ww + 2;
            xp1[j] = (nxt < 64 && valid[j])
                     ? xrow[j][(size_t)nxt * C_DIM] : 0.f;
        }
    }
}

// ---------------------------------------------------------------------------
extern "C" void kernel_launch(void* const* d_in, const int* in_sizes, int n_in,
                              void* d_out, int out_size)
{
    const float* x      = (const float*)d_in[0];
    const float* qkv_w  = (const float*)d_in[1];
    const float* proj_w = (const float*)d_in[2];
    const float* proj_b = (const float*)d_in[3];
    const float* lepe_w = (const float*)d_in[4];
    const float* lepe_b = (const float*)d_in[5];
    float* out = (float*)d_out;
    (void)in_sizes; (void)n_in; (void)out_size;

    void *x_h, *qkvw_h, *projw_h, *qkv_h, *comb_h;
    cudaGetSymbolAddress(&x_h, g_x_h);
    cudaGetSymbolAddress(&qkvw_h, g_qkvw_h);
    cudaGetSymbolAddress(&projw_h, g_projw_h);
    cudaGetSymbolAddress(&qkv_h, g_qkv_h);
    cudaGetSymbolAddress(&comb_h, g_comb_h);

    const int nx = M_TOTAL * C_DIM;
    const int nq = QKV_N * C_DIM;
    const int np = C_DIM * C_DIM;
    cvt_f32_f16_kernel<<<nx / 2048, 256>>>(x, (__half*)x_h, nx);
    cvt_f32_f16_kernel<<<(nq + 2047) / 2048, 256>>>(qkv_w, (__half*)qkvw_h, nq);
    cvt_f32_f16_kernel<<<(np + 2047) / 2048, 256>>>(proj_w, (__half*)projw_h, np);

    // qkv: n-tile 192 -> grid (6, 512)
    dim3 g_qkv_grid(QKV_N / 192, M_TOTAL / 128);
    gemm_h_kernel<3, true><<<g_qkv_grid, 192>>>(
        (const __half*)x_h, (const __half*)qkvw_h, nullptr, qkv_h, QKV_N);

    attn_kernel<<<B_DIM * 64 * N_HEADS, 128>>>();

    lepe_kernel<<<B_DIM * 64, C_DIM>>>(x, lepe_w, lepe_b);

    // proj: n-tile 192 -> grid (2, 512)
    dim3 g_proj_grid(C_DIM / 192, M_TOTAL / 128);
    gemm_h_kernel<3, false><<<g_proj_grid, 192>>>(
        (const __half*)comb_h, (const __half*)projw_h, proj_b, out, C_DIM);
}